// round 8
// baseline (speedup 1.0000x reference)
#include <cuda_runtime.h>
#include <cstdint>
#include <cstddef>

#define BB 64
#define TT 512
#define II 128
#define HH 512
#define NCLS 5

typedef unsigned long long u64;
typedef ulonglong2 ull2;

// Scratch — static __device__ arrays per allocation rules.
__device__ float g_xpA[(size_t)BB * TT * HH];
__device__ float g_xpB[(size_t)BB * TT * HH];
__device__ float g_ys[(size_t)BB * TT * HH];

// ---------------- packed f32x2 helpers ----------------
__device__ __forceinline__ u64 pk2(float x, float y) {
    u64 r; asm("mov.b64 %0, {%1,%2};" : "=l"(r) : "f"(x), "f"(y)); return r;
}
__device__ __forceinline__ float2 upk2(u64 v) {
    float2 f; asm("mov.b64 {%0,%1}, %2;" : "=f"(f.x), "=f"(f.y) : "l"(v)); return f;
}
__device__ __forceinline__ void fma2(u64 &d, u64 a, u64 b) {
    asm("fma.rn.f32x2 %0, %1, %2, %0;" : "+l"(d) : "l"(a), "l"(b));
}

// ---------------- cluster / mbarrier helpers ----------------
__device__ __forceinline__ uint32_t smem_u32(const void* p) {
    uint32_t a;
    asm("{ .reg .u64 t; cvta.to.shared.u64 t, %1; cvt.u32.u64 %0, t; }"
        : "=r"(a) : "l"(p));
    return a;
}
__device__ __forceinline__ uint32_t mapa_u32(uint32_t local, uint32_t rank) {
    uint32_t r;
    asm("mapa.shared::cluster.u32 %0, %1, %2;" : "=r"(r) : "r"(local), "r"(rank));
    return r;
}
__device__ __forceinline__ void mbar_init(uint32_t addr, uint32_t count) {
    asm volatile("mbarrier.init.shared.b64 [%0], %1;" :: "r"(addr), "r"(count) : "memory");
}
__device__ __forceinline__ void mbar_expect_tx(uint32_t addr, uint32_t bytes) {
    asm volatile("mbarrier.arrive.expect_tx.shared.b64 _, [%0], %1;"
                 :: "r"(addr), "r"(bytes) : "memory");
}
__device__ __forceinline__ void bulk_copy_cluster(uint32_t dst_cluster, uint32_t src_cta,
                                                  uint32_t bytes, uint32_t mbar_cluster) {
    asm volatile("cp.async.bulk.shared::cluster.shared::cta.mbarrier::complete_tx::bytes "
                 "[%0], [%1], %2, [%3];"
                 :: "r"(dst_cluster), "r"(src_cta), "r"(bytes), "r"(mbar_cluster) : "memory");
}
__device__ __forceinline__ void mbar_wait_cluster(uint32_t addr, uint32_t parity) {
    asm volatile(
        "{\n\t"
        ".reg .pred P;\n\t"
        "WLP%=:\n\t"
        "mbarrier.try_wait.parity.acquire.cluster.shared::cta.b64 P, [%0], %1, 0x989680;\n\t"
        "@P bra WDN%=;\n\t"
        "bra WLP%=;\n\t"
        "WDN%=:\n\t"
        "}"
        :: "r"(addr), "r"(parity) : "memory");
}
__device__ __forceinline__ void fence_proxy_async_cta() {
    asm volatile("fence.proxy.async.shared::cta;" ::: "memory");
}
__device__ __forceinline__ void cluster_sync_full() {
    asm volatile("barrier.cluster.arrive.aligned;" ::: "memory");
    asm volatile("barrier.cluster.wait.aligned;" ::: "memory");
}

// =======================================================================
// GEMM (layer 0 only, K=128): C = A @ W^T + b1 + b2, software pipelined
// =======================================================================
__global__ void __launch_bounds__(256, 1)
gemm_xproj(const float* __restrict__ A, const float* __restrict__ W,
           const float* __restrict__ b1, const float* __restrict__ b2,
           float* __restrict__ C, int K)
{
    __shared__ u64 As2[8][128];
    __shared__ u64 Bs2[8][128];

    const int tid = threadIdx.x;
    const int m0 = blockIdx.y * 128;
    const int n0 = blockIdx.x * 128;
    const int tx = tid & 15;
    const int ty = tid >> 4;
    const int r0  = tid >> 2;
    const int kq0 = tid & 3;

    u64 acc[8][8];
    #pragma unroll
    for (int i = 0; i < 8; i++)
        #pragma unroll
        for (int j = 0; j < 8; j++) acc[i][j] = 0ull;

    const float* pa0 = &A[(size_t)(m0 + r0)      * K + kq0 * 4];
    const float* pa1 = &A[(size_t)(m0 + 64 + r0) * K + kq0 * 4];
    const float* pw0 = &W[(size_t)(n0 + r0)      * K + kq0 * 4];
    const float* pw1 = &W[(size_t)(n0 + 64 + r0) * K + kq0 * 4];

    const int ktiles = K >> 4;
    float4 a0 = *(const float4*)pa0;
    float4 a1 = *(const float4*)pa1;
    float4 w0 = *(const float4*)pw0;
    float4 w1 = *(const float4*)pw1;

    for (int kt = 0; kt < ktiles; kt++) {
        __syncthreads();
        As2[kq0 * 2][r0]          = pk2(a0.x, a0.y);
        As2[kq0 * 2 + 1][r0]      = pk2(a0.z, a0.w);
        As2[kq0 * 2][64 + r0]     = pk2(a1.x, a1.y);
        As2[kq0 * 2 + 1][64 + r0] = pk2(a1.z, a1.w);
        Bs2[kq0 * 2][r0]          = pk2(w0.x, w0.y);
        Bs2[kq0 * 2 + 1][r0]      = pk2(w0.z, w0.w);
        Bs2[kq0 * 2][64 + r0]     = pk2(w1.x, w1.y);
        Bs2[kq0 * 2 + 1][64 + r0] = pk2(w1.z, w1.w);
        __syncthreads();

        if (kt + 1 < ktiles) {
            const int kb = (kt + 1) * 16;
            a0 = *(const float4*)(pa0 + kb);
            a1 = *(const float4*)(pa1 + kb);
            w0 = *(const float4*)(pw0 + kb);
            w1 = *(const float4*)(pw1 + kb);
        }

        #pragma unroll
        for (int k2 = 0; k2 < 8; k2++) {
            u64 af[8], bf[8];
            #pragma unroll
            for (int i = 0; i < 8; i++) af[i] = As2[k2][ty + 16 * i];
            #pragma unroll
            for (int j = 0; j < 8; j++) bf[j] = Bs2[k2][tx + 16 * j];
            #pragma unroll
            for (int i = 0; i < 8; i++)
                #pragma unroll
                for (int j = 0; j < 8; j++)
                    fma2(acc[i][j], af[i], bf[j]);
        }
    }

    float bias8[8];
    #pragma unroll
    for (int j = 0; j < 8; j++) {
        int n = n0 + tx + 16 * j;
        bias8[j] = b1[n] + b2[n];
    }
    #pragma unroll
    for (int i = 0; i < 8; i++) {
        const size_t m = (size_t)(m0 + ty + 16 * i);
        #pragma unroll
        for (int j = 0; j < 8; j++) {
            float2 p = upk2(acc[i][j]);
            C[m * HH + n0 + tx + 16 * j] = p.x + p.y + bias8[j];
        }
    }
}

// =======================================================================
// Fused recurrence (R4 exchange) + next-layer xproj in the latency bubble.
// 16 clusters x 8 CTAs; CTA r owns cols [64r,64r+64) of 4 batch chains.
// At step t the full h_{t-1} is in h_s[os]; besides the recurrence, each
// warp also computes its k-chunk partial of xp_next[t-1] = Wih_next @
// h_{t-1} (+ biases), staged into a second reduction buffer and streamed
// to xp_next. Wih_next==nullptr disables fusion (last layer).
// Dynamic smem: [wih 128KB][h_s 16KB][redv 8KB][redv2 8KB][out 2KB][bias][mbar]
// =======================================================================
#define SM_WIH   0
#define SM_HS    131072
#define SM_REDV  147456
#define SM_REDV2 155648
#define SM_OUT   163840
#define SM_BIAS  165888
#define SM_MBAR  166144
#define SM_TOTAL 166272

__global__ void __launch_bounds__(256, 1) __cluster_dims__(8, 1, 1)
rnn_fused(const float* __restrict__ xp, const float* __restrict__ Whh,
          const float* __restrict__ Wih_next,
          const float* __restrict__ bih_next, const float* __restrict__ bhh_next,
          float* __restrict__ xp_next, float* __restrict__ ys)
{
    extern __shared__ char dsm[];
    u64*   wih_s  = (u64*)(dsm + SM_WIH);            // [kpair 256][col 64]
    ull2*  hs     = (ull2*)(dsm + SM_HS);            // [buf2][chunk8][b4][kv16]
    float* redv   = (float*)(dsm + SM_REDV);         // [chunk8][b4][col64]
    float* redv2  = (float*)(dsm + SM_REDV2);        // [chunk8][b4][col64]
    float* out_s  = (float*)(dsm + SM_OUT);          // [buf2][b4][col64]
    float* bias_s = (float*)(dsm + SM_BIAS);         // [64]
    u64*   mbar   = (u64*)(dsm + SM_MBAR);           // [buf2][chunk8]

    const bool fuse = (Wih_next != nullptr);

    const int tid   = threadIdx.x;
    const int r     = blockIdx.x & 7;
    const int cl    = blockIdx.x >> 3;
    const int bg    = cl * 4;
    const int jbase = r * 64;

    const int jp = tid & 31;
    const int kc = tid >> 5;
    const int k0 = kc * 64;

    // ---- W_hh slice in registers, k-pair packed ----
    u64 wh[2][32];
    #pragma unroll
    for (int jj = 0; jj < 2; jj++) {
        const float* wrow = &Whh[(size_t)(jbase + jp + jj * 32) * HH + k0];
        #pragma unroll
        for (int kp = 0; kp < 32; kp++) {
            float2 wv = *(const float2*)&wrow[2 * kp];
            wh[jj][kp] = pk2(wv.x, wv.y);
        }
    }

    // ---- W_ih_next slice -> smem (k-pair packed, [kpair][col]) ----
    if (fuse) {
        for (int n = 0; n < 64; n++) {   // col = n, kp = tid (coalesced LDG)
            float2 wv = *(const float2*)&Wih_next[(size_t)(jbase + n) * HH + 2 * tid];
            wih_s[(size_t)tid * 64 + n] = pk2(wv.x, wv.y);
        }
        if (tid < 64)
            bias_s[tid] = bih_next[jbase + tid] + bhh_next[jbase + tid];
    }

    // ---- zero h buffers, init mbarriers + first expects ----
    {
        float4* hz = (float4*)hs;
        for (int i = tid; i < 2 * 8 * 4 * 16; i += 256)
            hz[i] = make_float4(0.f, 0.f, 0.f, 0.f);
    }
    const uint32_t mb_base = smem_u32(mbar);
    const uint32_t hbase   = smem_u32(hs);
    const uint32_t obase   = smem_u32(out_s);
    if (tid < 16) {
        mbar_init(mb_base + (uint32_t)tid * 8u, 1);
        mbar_expect_tx(mb_base + (uint32_t)tid * 8u, 1024u);
    }
    __syncthreads();
    cluster_sync_full();

    const uint32_t my_mb[2] = { mb_base + (uint32_t)kc * 8u,
                                mb_base + (uint32_t)(8 + kc) * 8u };
    int par0 = 0, par1 = 0;

    uint32_t dst_q = 0, rmb0 = 0, rmb1 = 0;
    if (tid < 8) {
        const uint32_t q = (uint32_t)tid;
        dst_q = mapa_u32(hbase, q) + (uint32_t)r * 1024u;
        rmb0 = mapa_u32(mb_base + (uint32_t)r * 8u, q);
        rmb1 = mapa_u32(mb_base + (uint32_t)(8 + r) * 8u, q);
    }

    // reduce-role mapping
    const int cb = tid >> 6;
    const int cj = tid & 63;
    const float* xp_ptr = &xp[((size_t)(bg + cb) * TT) * HH + jbase + cj];
    float* xpn_base = fuse ? &xp_next[((size_t)(bg + cb) * TT) * HH + jbase + cj] : nullptr;

    const u64* wps = wih_s + (size_t)(kc * 32) * 64;   // this chunk's 32 kpairs

    for (int t = 0; t < TT; t++) {
        const int os   = t & 1;
        const int wbuf = os ^ 1;

        const float xpv = __ldg(xp_ptr);

        if (t > 0) {
            if (os == 0) {
                mbar_wait_cluster(my_mb[0], par0);
                if (jp == 0) mbar_expect_tx(my_mb[0], 1024u);
                par0 ^= 1;
            } else {
                mbar_wait_cluster(my_mb[1], par1);
                if (jp == 0) mbar_expect_tx(my_mb[1], 1024u);
                par1 ^= 1;
            }
        }

        const ull2* hb = hs + (size_t)((os * 8 + kc) * 4) * 16;
        u64 racc[8];                    // [jj2][b4]
        #pragma unroll
        for (int i = 0; i < 8; i++) racc[i] = 0ull;

        const bool doX = fuse && (t > 0);
        if (doX) {
            u64 xacc[8];
            #pragma unroll
            for (int i = 0; i < 8; i++) xacc[i] = 0ull;
            #pragma unroll
            for (int kv = 0; kv < 16; kv++) {
                u64 wa0 = wps[(size_t)(2 * kv) * 64 + jp];
                u64 wa1 = wps[(size_t)(2 * kv + 1) * 64 + jp];
                u64 wb0 = wps[(size_t)(2 * kv) * 64 + 32 + jp];
                u64 wb1 = wps[(size_t)(2 * kv + 1) * 64 + 32 + jp];
                #pragma unroll
                for (int b = 0; b < 4; b++) {
                    ull2 hv = hb[b * 16 + kv];
                    fma2(racc[b],     wh[0][2 * kv],     hv.x);
                    fma2(racc[b],     wh[0][2 * kv + 1], hv.y);
                    fma2(racc[4 + b], wh[1][2 * kv],     hv.x);
                    fma2(racc[4 + b], wh[1][2 * kv + 1], hv.y);
                    fma2(xacc[b],     wa0, hv.x);
                    fma2(xacc[b],     wa1, hv.y);
                    fma2(xacc[4 + b], wb0, hv.x);
                    fma2(xacc[4 + b], wb1, hv.y);
                }
            }
            #pragma unroll
            for (int b = 0; b < 4; b++) {
                float2 p0 = upk2(xacc[b]);
                float2 p1 = upk2(xacc[4 + b]);
                redv2[(kc * 4 + b) * 64 + jp]      = p0.x + p0.y;
                redv2[(kc * 4 + b) * 64 + jp + 32] = p1.x + p1.y;
            }
        } else {
            #pragma unroll
            for (int kv = 0; kv < 16; kv++) {
                #pragma unroll
                for (int b = 0; b < 4; b++) {
                    ull2 hv = hb[b * 16 + kv];
                    fma2(racc[b],     wh[0][2 * kv],     hv.x);
                    fma2(racc[b],     wh[0][2 * kv + 1], hv.y);
                    fma2(racc[4 + b], wh[1][2 * kv],     hv.x);
                    fma2(racc[4 + b], wh[1][2 * kv + 1], hv.y);
                }
            }
        }

        #pragma unroll
        for (int b = 0; b < 4; b++) {
            float2 p0 = upk2(racc[b]);
            float2 p1 = upk2(racc[4 + b]);
            redv[(kc * 4 + b) * 64 + jp]      = p0.x + p0.y;
            redv[(kc * 4 + b) * 64 + jp + 32] = p1.x + p1.y;
        }
        __syncthreads();

        // ---- reduce recurrence -> h_t slice ----
        {
            float s = xpv;
            #pragma unroll
            for (int c = 0; c < 8; c++) s += redv[(c * 4 + cb) * 64 + cj];
            s = fmaxf(s, 0.f);
            out_s[(os * 4 + cb) * 64 + cj] = s;
            if (t == TT - 1)
                ys[(((size_t)(bg + cb) * TT) + (TT - 1)) * HH + jbase + cj] = s;
        }
        // ---- reduce xproj -> xp_next[t-1] ----
        if (doX) {
            float s2 = bias_s[cj];
            #pragma unroll
            for (int c = 0; c < 8; c++) s2 += redv2[(c * 4 + cb) * 64 + cj];
            xpn_base[(size_t)(t - 1) * HH] = s2;
        }
        __syncthreads();

        // ---- async bulk push (all t, incl. 511 for the epilogue) ----
        if (tid < 8) {
            fence_proxy_async_cta();
            bulk_copy_cluster(dst_q + (uint32_t)wbuf * 8192u,
                              obase + (uint32_t)os * 1024u,
                              1024u, wbuf ? rmb1 : rmb0);
        }

        xp_ptr += HH;
    }

    // ---- epilogue: h_511 lands in buf 0; compute xp_next[511] ----
    mbar_wait_cluster(my_mb[0], par0);     // also guarantees inbound settled
    if (fuse) {
        const ull2* hb = hs + (size_t)(kc * 4) * 16;   // buf 0, chunk kc
        u64 xacc[8];
        #pragma unroll
        for (int i = 0; i < 8; i++) xacc[i] = 0ull;
        #pragma unroll
        for (int kv = 0; kv < 16; kv++) {
            u64 wa0 = wps[(size_t)(2 * kv) * 64 + jp];
            u64 wa1 = wps[(size_t)(2 * kv + 1) * 64 + jp];
            u64 wb0 = wps[(size_t)(2 * kv) * 64 + 32 + jp];
            u64 wb1 = wps[(size_t)(2 * kv + 1) * 64 + 32 + jp];
            #pragma unroll
            for (int b = 0; b < 4; b++) {
                ull2 hv = hb[b * 16 + kv];
                fma2(xacc[b],     wa0, hv.x);
                fma2(xacc[b],     wa1, hv.y);
                fma2(xacc[4 + b], wb0, hv.x);
                fma2(xacc[4 + b], wb1, hv.y);
            }
        }
        #pragma unroll
        for (int b = 0; b < 4; b++) {
            float2 p0 = upk2(xacc[b]);
            float2 p1 = upk2(xacc[4 + b]);
            redv2[(kc * 4 + b) * 64 + jp]      = p0.x + p0.y;
            redv2[(kc * 4 + b) * 64 + jp + 32] = p1.x + p1.y;
        }
        __syncthreads();
        {
            float s2 = bias_s[cj];
            #pragma unroll
            for (int c = 0; c < 8; c++) s2 += redv2[(c * 4 + cb) * 64 + cj];
            xpn_base[(size_t)(TT - 1) * HH] = s2;
        }
    }

    cluster_sync_full();
}

// =======================================================================
// Final projection
// =======================================================================
__global__ void proj_kernel(const float* __restrict__ ys,
                            const float* __restrict__ Wout,
                            const float* __restrict__ bout,
                            float* __restrict__ out)
{
    const int b    = blockIdx.x;
    const int c    = threadIdx.y;
    const int lane = threadIdx.x;
    const float* hrow = &ys[((size_t)b * TT + (TT - 1)) * HH];
    const float* wrow = &Wout[(size_t)c * HH];
    float s = 0.f;
    for (int k = lane; k < HH; k += 32) s += hrow[k] * wrow[k];
    #pragma unroll
    for (int o = 16; o > 0; o >>= 1) s += __shfl_down_sync(0xffffffffu, s, o);
    if (lane == 0) out[b * NCLS + c] = s + bout[c];
}

// =======================================================================
extern "C" void kernel_launch(void* const* d_in, const int* in_sizes, int n_in,
                              void* d_out, int out_size)
{
    (void)in_sizes; (void)n_in; (void)out_size;
    const float* x    = (const float*)d_in[0];
    const float* Wih[3] = {(const float*)d_in[1], (const float*)d_in[5], (const float*)d_in[9]};
    const float* Whh[3] = {(const float*)d_in[2], (const float*)d_in[6], (const float*)d_in[10]};
    const float* bih[3] = {(const float*)d_in[3], (const float*)d_in[7], (const float*)d_in[11]};
    const float* bhh[3] = {(const float*)d_in[4], (const float*)d_in[8], (const float*)d_in[12]};
    const float* Wout = (const float*)d_in[13];
    const float* bout = (const float*)d_in[14];
    float* out = (float*)d_out;

    float *xpA = nullptr, *xpB = nullptr, *ysPtr = nullptr;
    cudaGetSymbolAddress((void**)&xpA, g_xpA);
    cudaGetSymbolAddress((void**)&xpB, g_xpB);
    cudaGetSymbolAddress((void**)&ysPtr, g_ys);

    cudaFuncSetAttribute(rnn_fused, cudaFuncAttributeMaxDynamicSharedMemorySize, SM_TOTAL);

    // layer 0 xproj (K=128) via standalone GEMM
    gemm_xproj<<<dim3(HH / 128, (BB * TT) / 128), 256>>>(x, Wih[0], bih[0], bhh[0], xpA, II);
    // layer 0 recurrence + fused xproj for layer 1
    rnn_fused<<<128, 256, SM_TOTAL>>>(xpA, Whh[0], Wih[1], bih[1], bhh[1], xpB, ysPtr);
    // layer 1 recurrence + fused xproj for layer 2
    rnn_fused<<<128, 256, SM_TOTAL>>>(xpB, Whh[1], Wih[2], bih[2], bhh[2], xpA, ysPtr);
    // layer 2 recurrence (no fusion)
    rnn_fused<<<128, 256, SM_TOTAL>>>(xpA, Whh[2], nullptr, nullptr, nullptr, nullptr, ysPtr);

    proj_kernel<<<64, dim3(32, 5)>>>(ysPtr, Wout, bout, out);
}

// round 9
// speedup vs baseline: 1.1971x; 1.1971x over previous
#include <cuda_runtime.h>
#include <cstdint>
#include <cstddef>

#define BB 64
#define TT 512
#define II 128
#define HH 512
#define NCLS 5

#define F_HAVEA 1
#define F_HAVEB 2
#define F_GATEA 4

typedef unsigned long long u64;
typedef ulonglong2 ull2;

// Scratch — static __device__ arrays per allocation rules.
__device__ float g_xpA[(size_t)BB * TT * HH];
__device__ float g_xpB[(size_t)BB * TT * HH];
__device__ float g_ys[(size_t)BB * TT * HH];

// Cross-CTA coordination (reset by reset_counters before every mega launch).
__device__ int g_jcA;        // phase-A job queue head
__device__ int g_jcB;        // phase-B job queue head
__device__ int g_dA[4];      // phase-A completed-jobs count per t-block
__device__ int g_prog[64];   // recurrence progress per (cluster, rank)

// ---------------- packed f32x2 helpers ----------------
__device__ __forceinline__ u64 pk2(float x, float y) {
    u64 r; asm("mov.b64 %0, {%1,%2};" : "=l"(r) : "f"(x), "f"(y)); return r;
}
__device__ __forceinline__ float2 upk2(u64 v) {
    float2 f; asm("mov.b64 {%0,%1}, %2;" : "=f"(f.x), "=f"(f.y) : "l"(v)); return f;
}
__device__ __forceinline__ void fma2(u64 &d, u64 a, u64 b) {
    asm("fma.rn.f32x2 %0, %1, %2, %0;" : "+l"(d) : "l"(a), "l"(b));
}

// ---------------- cluster / mbarrier helpers ----------------
__device__ __forceinline__ uint32_t smem_u32(const void* p) {
    uint32_t a;
    asm("{ .reg .u64 t; cvta.to.shared.u64 t, %1; cvt.u32.u64 %0, t; }"
        : "=r"(a) : "l"(p));
    return a;
}
__device__ __forceinline__ uint32_t mapa_u32(uint32_t local, uint32_t rank) {
    uint32_t r;
    asm("mapa.shared::cluster.u32 %0, %1, %2;" : "=r"(r) : "r"(local), "r"(rank));
    return r;
}
__device__ __forceinline__ void mbar_init(uint32_t addr, uint32_t count) {
    asm volatile("mbarrier.init.shared.b64 [%0], %1;" :: "r"(addr), "r"(count) : "memory");
}
__device__ __forceinline__ void mbar_expect_tx(uint32_t addr, uint32_t bytes) {
    asm volatile("mbarrier.arrive.expect_tx.shared.b64 _, [%0], %1;"
                 :: "r"(addr), "r"(bytes) : "memory");
}
__device__ __forceinline__ void bulk_copy_cluster(uint32_t dst_cluster, uint32_t src_cta,
                                                  uint32_t bytes, uint32_t mbar_cluster) {
    asm volatile("cp.async.bulk.shared::cluster.shared::cta.mbarrier::complete_tx::bytes "
                 "[%0], [%1], %2, [%3];"
                 :: "r"(dst_cluster), "r"(src_cta), "r"(bytes), "r"(mbar_cluster) : "memory");
}
__device__ __forceinline__ void mbar_wait_cluster(uint32_t addr, uint32_t parity) {
    asm volatile(
        "{\n\t"
        ".reg .pred P;\n\t"
        "WLP%=:\n\t"
        "mbarrier.try_wait.parity.acquire.cluster.shared::cta.b64 P, [%0], %1, 0x989680;\n\t"
        "@P bra WDN%=;\n\t"
        "bra WLP%=;\n\t"
        "WDN%=:\n\t"
        "}"
        :: "r"(addr), "r"(parity) : "memory");
}
__device__ __forceinline__ void fence_proxy_async_cta() {
    asm volatile("fence.proxy.async.shared::cta;" ::: "memory");
}
__device__ __forceinline__ void cluster_sync_full() {
    asm volatile("barrier.cluster.arrive.aligned;" ::: "memory");
    asm volatile("barrier.cluster.wait.aligned;" ::: "memory");
}

// =======================================================================
// One 128x128 GEMM tile: C[0:128, 0:128] += A[0:128, 0:K] @ W[0:128, 0:K]^T
// + b1 + b2.  A row stride K, W row stride K, C row stride HH.
// Software pipelined; all 256 threads of the CTA participate.
// =======================================================================
__device__ __forceinline__ void gemm_tile(
    const float* __restrict__ A, const float* __restrict__ W,
    const float* __restrict__ b1, const float* __restrict__ b2,
    float* __restrict__ C, int K,
    u64 (*As2)[128], u64 (*Bs2)[128])
{
    const int tid = threadIdx.x;
    const int tx = tid & 15;
    const int ty = tid >> 4;
    const int r0  = tid >> 2;
    const int kq0 = tid & 3;

    u64 acc[8][8];
    #pragma unroll
    for (int i = 0; i < 8; i++)
        #pragma unroll
        for (int j = 0; j < 8; j++) acc[i][j] = 0ull;

    const float* pa0 = &A[(size_t)r0        * K + kq0 * 4];
    const float* pa1 = &A[(size_t)(64 + r0) * K + kq0 * 4];
    const float* pw0 = &W[(size_t)r0        * K + kq0 * 4];
    const float* pw1 = &W[(size_t)(64 + r0) * K + kq0 * 4];

    const int ktiles = K >> 4;
    float4 a0 = *(const float4*)pa0;
    float4 a1 = *(const float4*)pa1;
    float4 w0 = *(const float4*)pw0;
    float4 w1 = *(const float4*)pw1;

    for (int kt = 0; kt < ktiles; kt++) {
        __syncthreads();
        As2[kq0 * 2][r0]          = pk2(a0.x, a0.y);
        As2[kq0 * 2 + 1][r0]      = pk2(a0.z, a0.w);
        As2[kq0 * 2][64 + r0]     = pk2(a1.x, a1.y);
        As2[kq0 * 2 + 1][64 + r0] = pk2(a1.z, a1.w);
        Bs2[kq0 * 2][r0]          = pk2(w0.x, w0.y);
        Bs2[kq0 * 2 + 1][r0]      = pk2(w0.z, w0.w);
        Bs2[kq0 * 2][64 + r0]     = pk2(w1.x, w1.y);
        Bs2[kq0 * 2 + 1][64 + r0] = pk2(w1.z, w1.w);
        __syncthreads();

        if (kt + 1 < ktiles) {
            const int kb = (kt + 1) * 16;
            a0 = *(const float4*)(pa0 + kb);
            a1 = *(const float4*)(pa1 + kb);
            w0 = *(const float4*)(pw0 + kb);
            w1 = *(const float4*)(pw1 + kb);
        }

        #pragma unroll
        for (int k2 = 0; k2 < 8; k2++) {
            u64 af[8], bf[8];
            #pragma unroll
            for (int i = 0; i < 8; i++) af[i] = As2[k2][ty + 16 * i];
            #pragma unroll
            for (int j = 0; j < 8; j++) bf[j] = Bs2[k2][tx + 16 * j];
            #pragma unroll
            for (int i = 0; i < 8; i++)
                #pragma unroll
                for (int j = 0; j < 8; j++)
                    fma2(acc[i][j], af[i], bf[j]);
        }
    }

    float bias8[8];
    #pragma unroll
    for (int j = 0; j < 8; j++) {
        int n = tx + 16 * j;
        bias8[j] = b1[n] + b2[n];
    }
    #pragma unroll
    for (int i = 0; i < 8; i++) {
        const size_t m = (size_t)(ty + 16 * i);
        #pragma unroll
        for (int j = 0; j < 8; j++) {
            float2 p = upk2(acc[i][j]);
            C[m * HH + tx + 16 * j] = p.x + p.y + bias8[j];
        }
    }
}

// Run phase-B jobs (xproj of next layer from ys, K=512, gated on g_prog).
__device__ void run_phaseB(const float* __restrict__ ys,
                           const float* __restrict__ WihB,
                           const float* __restrict__ biB,
                           const float* __restrict__ bhB,
                           float* __restrict__ CB,
                           u64 (*As2)[128], u64 (*Bs2)[128])
{
    __shared__ int s_job;
    for (;;) {
        if (threadIdx.x == 0)
            s_job = atomicAdd(&g_jcB, 1);
        __syncthreads();
        const int j = s_job;
        if (j >= 1024) break;
        const int tb = j >> 8, r8 = j & 255, b = r8 >> 2, nt = r8 & 3;
        const int thr = tb * 128 + 128;
        if (threadIdx.x == 0) {
            const int cb8 = (b >> 3) * 8;
            #pragma unroll
            for (int q = 0; q < 8; q++) {
                while (((volatile int*)g_prog)[cb8 + q] < thr)
                    __nanosleep(128);
            }
            __threadfence();
        }
        __syncthreads();
        gemm_tile(ys + (size_t)(b * TT + tb * 128) * HH,
                  WihB + (size_t)(nt * 128) * HH,
                  biB + nt * 128, bhB + nt * 128,
                  CB + (size_t)(b * TT + tb * 128) * HH + nt * 128,
                  HH, As2, Bs2);
        __syncthreads();
    }
}

// =======================================================================
// Mega kernel: clusters 0..7 = recurrence (R7 two-group scheme, 8 batches
// per cluster); clusters >= 8 = GEMM workers (phase A = this layer's xproj
// from x, ungated; phase B = next layer's xproj from ys, gated on g_prog).
// Recurrence CTAs join phase B after finishing.
// =======================================================================
__global__ void __launch_bounds__(256, 1) __cluster_dims__(8, 1, 1)
mega(const float* __restrict__ xp, const float* __restrict__ Whh,
     float* __restrict__ ys,
     const float* __restrict__ Ax,  const float* __restrict__ WihA,
     const float* __restrict__ biA, const float* __restrict__ bhA,
     float* __restrict__ CA, int KA,
     const float* __restrict__ WihB, const float* __restrict__ biB,
     const float* __restrict__ bhB,  float* __restrict__ CB,
     int flags)
{
    __shared__ ull2 h_s[2][2][8][4][16];
    __shared__ float redv[8][4][64];
    __shared__ __align__(16) float out_s[2][2][4][64];
    __shared__ __align__(8) u64 mbar[2][2][8];
    __shared__ u64 As2[8][128];
    __shared__ u64 Bs2[8][128];

    const int tid = threadIdx.x;
    const int cl  = blockIdx.x >> 3;

    if (cl >= 8) {
        // ======================= GEMM role =======================
        if (flags & F_HAVEA) {
            __shared__ int s_job;
            for (;;) {
                if (tid == 0) s_job = atomicAdd(&g_jcA, 1);
                __syncthreads();
                const int j = s_job;
                if (j >= 1024) break;
                const int tb = j >> 8, r8 = j & 255, b = r8 >> 2, nt = r8 & 3;
                gemm_tile(Ax + (size_t)(b * TT + tb * 128) * KA,
                          WihA + (size_t)(nt * 128) * KA,
                          biA + nt * 128, bhA + nt * 128,
                          CA + (size_t)(b * TT + tb * 128) * HH + nt * 128,
                          KA, As2, Bs2);
                __syncthreads();
                __threadfence();
                if (tid == 0) atomicAdd(&g_dA[tb], 1);
                __syncthreads();
            }
        }
        if (flags & F_HAVEB)
            run_phaseB(ys, WihB, biB, bhB, CB, As2, Bs2);
        return;
    }

    // ======================= recurrence role =======================
    const int r     = blockIdx.x & 7;
    const int bg    = cl * 8;
    const int jbase = r * 64;
    const bool gateA = (flags & F_GATEA) != 0;

    const int jp = tid & 31;
    const int kc = tid >> 5;
    const int k0 = kc * 64;

    u64 w[2][32];
    #pragma unroll
    for (int jj = 0; jj < 2; jj++) {
        const float* wrow = &Whh[(size_t)(jbase + jp + jj * 32) * HH + k0];
        #pragma unroll
        for (int kp = 0; kp < 32; kp++) {
            float2 wv = *(const float2*)&wrow[2 * kp];
            w[jj][kp] = pk2(wv.x, wv.y);
        }
    }

    {
        float4* hs = (float4*)h_s;
        for (int i = tid; i < 2 * 2 * 8 * 4 * 16; i += 256)
            hs[i] = make_float4(0.f, 0.f, 0.f, 0.f);
    }
    const uint32_t mb_base = smem_u32(&mbar[0][0][0]);
    const uint32_t hbase   = smem_u32(&h_s[0][0][0][0][0]);
    const uint32_t obase   = smem_u32(&out_s[0][0][0][0]);
    if (tid < 32) {
        mbar_init(mb_base + (uint32_t)tid * 8u, 1);
        mbar_expect_tx(mb_base + (uint32_t)tid * 8u, 1024u);
    }
    __syncthreads();
    cluster_sync_full();

    uint32_t my_mb[2][2];
    #pragma unroll
    for (int g = 0; g < 2; g++)
        #pragma unroll
        for (int b = 0; b < 2; b++)
            my_mb[g][b] = mb_base + (uint32_t)(((g * 2 + b) * 8 + kc)) * 8u;
    int par[2][2] = {{0, 0}, {0, 0}};

    uint32_t dst_q = 0;
    uint32_t rmb[2][2];
    if (tid < 8) {
        const uint32_t q = (uint32_t)tid;
        dst_q = mapa_u32(hbase, q) + (uint32_t)r * 1024u;
        #pragma unroll
        for (int g = 0; g < 2; g++)
            #pragma unroll
            for (int b = 0; b < 2; b++)
                rmb[g][b] = mapa_u32(mb_base + (uint32_t)(((g * 2 + b) * 8 + r)) * 8u, q);
    }

    const int cb = tid >> 6;
    const int cj = tid & 63;
    const float* xp_p[2];
    float*       ys_p[2];
    #pragma unroll
    for (int g = 0; g < 2; g++) {
        xp_p[g] = &xp[((size_t)(bg + g * 4 + cb) * TT) * HH + jbase + cj];
        ys_p[g] = &ys[((size_t)(bg + g * 4 + cb) * TT) * HH + jbase + cj];
    }

    for (int t = 0; t < TT; t++) {
        const int os   = t & 1;
        const int wbuf = os ^ 1;
        const bool push = (t + 1 < TT);

        // gate on phase-A xproj availability (launch 0 only)
        if (gateA && (t & 127) == 0) {
            if (tid == 0) {
                while (((volatile int*)g_dA)[t >> 7] < 256)
                    __nanosleep(128);
                __threadfence();
            }
            __syncthreads();
        }

        float xpv[2];
        xpv[0] = __ldg(xp_p[0]);
        xpv[1] = __ldg(xp_p[1]);

        #pragma unroll
        for (int g = 0; g < 2; g++) {
            if (t > 0) {
                mbar_wait_cluster(my_mb[g][os], par[g][os]);
                if (jp == 0) mbar_expect_tx(my_mb[g][os], 1024u);
                par[g][os] ^= 1;
            }

            const ull2* hb = &h_s[g][os][kc][0][0];
            u64 acc0[4], acc1[4];
            #pragma unroll
            for (int b = 0; b < 4; b++) {
                u64 a0 = 0ull, a1 = 0ull;
                #pragma unroll
                for (int kv = 0; kv < 16; kv++) {
                    ull2 hv = hb[b * 16 + kv];
                    fma2(a0, w[0][2 * kv],     hv.x);
                    fma2(a0, w[0][2 * kv + 1], hv.y);
                    fma2(a1, w[1][2 * kv],     hv.x);
                    fma2(a1, w[1][2 * kv + 1], hv.y);
                }
                acc0[b] = a0; acc1[b] = a1;
            }

            #pragma unroll
            for (int b = 0; b < 4; b++) {
                float2 p0 = upk2(acc0[b]);
                float2 p1 = upk2(acc1[b]);
                redv[kc][b][jp]      = p0.x + p0.y;
                redv[kc][b][jp + 32] = p1.x + p1.y;
            }
            __syncthreads();

            {
                float s = xpv[g];
                #pragma unroll
                for (int c = 0; c < 8; c++) s += redv[c][cb][cj];
                s = fmaxf(s, 0.f);
                out_s[g][os][cb][cj] = s;
                *ys_p[g] = s;
                ys_p[g] += HH;
            }
            __syncthreads();

            if (push && tid < 8) {
                fence_proxy_async_cta();
                bulk_copy_cluster(dst_q + (uint32_t)g * 16384u + (uint32_t)wbuf * 8192u,
                                  obase + (uint32_t)g * 2048u + (uint32_t)os * 1024u,
                                  1024u, rmb[g][wbuf]);
            }
        }

        // publish recurrence progress (every 32 steps; ys stores are
        // ordered before the preceding __syncthreads, fence makes them
        // visible before the flag update)
        if ((t & 31) == 31 && tid == 0) {
            __threadfence();
            ((volatile int*)g_prog)[cl * 8 + r] = t + 1;
        }

        xp_p[0] += HH;
        xp_p[1] += HH;
    }

    cluster_sync_full();

    // join the phase-B job queue to absorb the tail
    if (flags & F_HAVEB)
        run_phaseB(ys, WihB, biB, bhB, CB, As2, Bs2);
}

// =======================================================================
__global__ void reset_counters() {
    const int i = threadIdx.x;
    if (i == 0) { g_jcA = 0; g_jcB = 0; }
    if (i < 4) g_dA[i] = 0;
    if (i < 64) g_prog[i] = 0;
}

// =======================================================================
// Final projection
// =======================================================================
__global__ void proj_kernel(const float* __restrict__ ys,
                            const float* __restrict__ Wout,
                            const float* __restrict__ bout,
                            float* __restrict__ out)
{
    const int b    = blockIdx.x;
    const int c    = threadIdx.y;
    const int lane = threadIdx.x;
    const float* hrow = &ys[((size_t)b * TT + (TT - 1)) * HH];
    const float* wrow = &Wout[(size_t)c * HH];
    float s = 0.f;
    for (int k = lane; k < HH; k += 32) s += hrow[k] * wrow[k];
    #pragma unroll
    for (int o = 16; o > 0; o >>= 1) s += __shfl_down_sync(0xffffffffu, s, o);
    if (lane == 0) out[b * NCLS + c] = s + bout[c];
}

// =======================================================================
extern "C" void kernel_launch(void* const* d_in, const int* in_sizes, int n_in,
                              void* d_out, int out_size)
{
    (void)in_sizes; (void)n_in; (void)out_size;
    const float* x    = (const float*)d_in[0];
    const float* Wih[3] = {(const float*)d_in[1], (const float*)d_in[5], (const float*)d_in[9]};
    const float* Whh[3] = {(const float*)d_in[2], (const float*)d_in[6], (const float*)d_in[10]};
    const float* bih[3] = {(const float*)d_in[3], (const float*)d_in[7], (const float*)d_in[11]};
    const float* bhh[3] = {(const float*)d_in[4], (const float*)d_in[8], (const float*)d_in[12]};
    const float* Wout = (const float*)d_in[13];
    const float* bout = (const float*)d_in[14];
    float* out = (float*)d_out;

    float *xpA = nullptr, *xpB = nullptr, *ysPtr = nullptr;
    cudaGetSymbolAddress((void**)&xpA, g_xpA);
    cudaGetSymbolAddress((void**)&xpB, g_xpB);
    cudaGetSymbolAddress((void**)&ysPtr, g_ys);

    // Layer 0: phase A computes xp0 from x (gating rnn0), phase B computes
    // xp1 from ys0 as it is produced.
    reset_counters<<<1, 64>>>();
    mega<<<144, 256>>>(xpA, Whh[0], ysPtr,
                       x, Wih[0], bih[0], bhh[0], xpA, II,
                       Wih[1], bih[1], bhh[1], xpB,
                       F_HAVEA | F_HAVEB | F_GATEA);

    // Layer 1: xp1 ready; phase B computes xp2 from ys1.
    reset_counters<<<1, 64>>>();
    mega<<<144, 256>>>(xpB, Whh[1], ysPtr,
                       nullptr, nullptr, nullptr, nullptr, nullptr, 0,
                       Wih[2], bih[2], bhh[2], xpA,
                       F_HAVEB);

    // Layer 2: recurrence only.
    mega<<<64, 256>>>(xpA, Whh[2], ysPtr,
                      nullptr, nullptr, nullptr, nullptr, nullptr, 0,
                      nullptr, nullptr, nullptr, nullptr,
                      0);

    proj_kernel<<<64, dim3(32, 5)>>>(ysPtr, Wout, bout, out);
}